// round 4
// baseline (speedup 1.0000x reference)
#include <cuda_runtime.h>
#include <cstdint>

#define F_DIM    132
#define M_TOTAL  24
#define D_IN     136
#define BM       128
#define WST      148   // padded W row stride (floats): 136 data + 8 zero cols + 4 pad
#define AST      140   // padded A row stride (floats): 136 data + 4 pad
#define NTHREADS 288   // 16 row-groups x 18 col-groups (cols padded to 144)
#define SMEM_FLOATS (D_IN * WST + BM * AST)
#define SMEM_BYTES  (SMEM_FLOATS * 4)

typedef unsigned long long u64;

__device__ __forceinline__ u64 pack2(float v) {
    u64 r;
    asm("mov.b64 %0, {%1, %1};" : "=l"(r) : "f"(v));
    return r;
}

__device__ __forceinline__ u64 fma2(u64 a, u64 b, u64 c) {
    u64 d;
    asm("fma.rn.f32x2 %0, %1, %2, %3;" : "=l"(d) : "l"(a), "l"(b), "l"(c));
    return d;
}

__device__ __forceinline__ float lo32(u64 v) { return __uint_as_float((unsigned)(v & 0xffffffffu)); }
__device__ __forceinline__ float hi32(u64 v) { return __uint_as_float((unsigned)(v >> 32)); }

__global__ __launch_bounds__(NTHREADS, 1)
void exchange_block_kernel(const float* __restrict__ x,
                           const float* __restrict__ ev,
                           const float* __restrict__ W,
                           const float* __restrict__ b,
                           float* __restrict__ out,
                           int n, int numTiles)
{
    extern __shared__ float smem[];
    float* Ws = smem;               // [D_IN][WST]
    float* As = smem + D_IN * WST;  // [BM][AST]

    const int tid = threadIdx.x;

    // ---- Load W into shared once (persistent block). 136 rows x 34 float4. ----
    for (int idx = tid; idx < D_IN * 34; idx += NTHREADS) {
        int k  = idx / 34;
        int c4 = idx % 34;
        float4 v = *(const float4*)(W + k * D_IN + c4 * 4);
        *(float4*)(Ws + k * WST + c4 * 4) = v;
    }
    // Zero padded output columns 136..143 (they are computed but discarded).
    for (int idx = tid; idx < D_IN * 2; idx += NTHREADS) {
        int k  = idx / 2;
        int c4 = idx % 2;
        *(float4*)(Ws + k * WST + 136 + c4 * 4) = make_float4(0.f, 0.f, 0.f, 0.f);
    }

    const int ty = tid / 18;  // 0..15 : row group (8 rows each)
    const int tx = tid % 18;  // 0..17 : col group (8 cols each, padded to 144)

    float* out1 = out;                         // [n][132]
    float* out2 = out + (size_t)n * F_DIM;     // [n][24]

    for (int tile = blockIdx.x; tile < numTiles; tile += gridDim.x) {
        const int rowBase = tile * BM;

        __syncthreads();  // W ready (iter 0) / previous tile's compute done

        // ---- Stage A tile: x part (33 float4 per row) ----
        for (int idx = tid; idx < BM * 33; idx += NTHREADS) {
            int r   = idx / 33;
            int c4  = idx % 33;
            int row = rowBase + r;
            float4 v = (row < n) ? *(const float4*)(x + (size_t)row * F_DIM + c4 * 4)
                                 : make_float4(0.f, 0.f, 0.f, 0.f);
            *(float4*)(As + r * AST + c4 * 4) = v;
        }
        // ---- contr: per-segment sum of ev^2 -> A cols 132..135 ----
        for (int r = tid; r < BM; r += NTHREADS) {
            int row = rowBase + r;
            float4 c;
            if (row < n) {
                const float* e = ev + (size_t)row * M_TOTAL;
                float s0 = 0.f, s1 = 0.f, s2 = 0.f, s3 = 0.f;
                #pragma unroll
                for (int m = 0;  m < 3;  m++) s0 += e[m] * e[m];
                #pragma unroll
                for (int m = 3;  m < 8;  m++) s1 += e[m] * e[m];
                #pragma unroll
                for (int m = 8;  m < 15; m++) s2 += e[m] * e[m];
                #pragma unroll
                for (int m = 15; m < 24; m++) s3 += e[m] * e[m];
                c = make_float4(s0, s1, s2, s3);
            } else {
                c = make_float4(0.f, 0.f, 0.f, 0.f);
            }
            *(float4*)(As + r * AST + F_DIM) = c;
        }
        __syncthreads();

        // ---- Main compute: 8 rows x 8 cols per thread, f32x2 packed FMA ----
        u64 acc[8][4];
        #pragma unroll
        for (int i = 0; i < 8; i++)
            #pragma unroll
            for (int p = 0; p < 4; p++)
                acc[i][p] = 0ull;  // bits of (+0.0f, +0.0f)

        const float* arow = As + (ty * 8) * AST;

        #pragma unroll 1
        for (int k0 = 0; k0 < D_IN; k0 += 4) {
            float4 a4[8];
            #pragma unroll
            for (int i = 0; i < 8; i++)
                a4[i] = *(const float4*)(arow + i * AST + k0);

            #pragma unroll
            for (int kk = 0; kk < 4; kk++) {
                const float* wrow = Ws + (k0 + kk) * WST + tx * 8;
                ulonglong2 wA = *(const ulonglong2*)(wrow);
                ulonglong2 wB = *(const ulonglong2*)(wrow + 4);
                #pragma unroll
                for (int i = 0; i < 8; i++) {
                    float a = (kk == 0) ? a4[i].x : (kk == 1) ? a4[i].y
                            : (kk == 2) ? a4[i].z : a4[i].w;
                    u64 aa = pack2(a);
                    acc[i][0] = fma2(aa, wA.x, acc[i][0]);
                    acc[i][1] = fma2(aa, wA.y, acc[i][1]);
                    acc[i][2] = fma2(aa, wB.x, acc[i][2]);
                    acc[i][3] = fma2(aa, wB.y, acc[i][3]);
                }
            }
        }

        // ---- Epilogue ----
        if (tx < 17) {  // tx==17 covers padded cols 136..143: discard
            const int c0 = tx * 8;
            #pragma unroll
            for (int i = 0; i < 8; i++) {
                int row = rowBase + ty * 8 + i;
                if (row >= n) break;
                float y[8];
                #pragma unroll
                for (int p = 0; p < 4; p++) {
                    y[2 * p]     = lo32(acc[i][p]);
                    y[2 * p + 1] = hi32(acc[i][p]);
                }
                if (c0 + 8 <= F_DIM) {
                    float4 v0 = make_float4(y[0] + b[c0],     y[1] + b[c0 + 1],
                                            y[2] + b[c0 + 2], y[3] + b[c0 + 3]);
                    float4 v1 = make_float4(y[4] + b[c0 + 4], y[5] + b[c0 + 5],
                                            y[6] + b[c0 + 6], y[7] + b[c0 + 7]);
                    float* o = out1 + (size_t)row * F_DIM + c0;
                    *(float4*)(o)     = v0;
                    *(float4*)(o + 4) = v1;
                } else {
                    // tx==16: cols 128..131 -> out1; cols 132..135 -> cev gating
                    float4 v0 = make_float4(y[0] + b[128], y[1] + b[129],
                                            y[2] + b[130], y[3] + b[131]);
                    *(float4*)(out1 + (size_t)row * F_DIM + 128) = v0;

                    float cev0 = y[4] + b[132];
                    float cev1 = y[5] + b[133];
                    float cev2 = y[6] + b[134];
                    float cev3 = y[7] + b[135];
                    const float* e  = ev   + (size_t)row * M_TOTAL;
                    float*       o2 = out2 + (size_t)row * M_TOTAL;
                    #pragma unroll
                    for (int m = 0;  m < 3;  m++) o2[m] = cev0 * e[m];
                    #pragma unroll
                    for (int m = 3;  m < 8;  m++) o2[m] = cev1 * e[m];
                    #pragma unroll
                    for (int m = 8;  m < 15; m++) o2[m] = cev2 * e[m];
                    #pragma unroll
                    for (int m = 15; m < 24; m++) o2[m] = cev3 * e[m];
                }
            }
        }
    }
}

extern "C" void kernel_launch(void* const* d_in, const int* in_sizes, int n_in,
                              void* d_out, int out_size)
{
    const float* x  = (const float*)d_in[0];
    const float* ev = (const float*)d_in[1];
    const float* W  = (const float*)d_in[2];
    const float* b  = (const float*)d_in[3];
    float* out = (float*)d_out;

    const int n = in_sizes[0] / F_DIM;          // 500000
    const int numTiles = (n + BM - 1) / BM;

    cudaFuncSetAttribute(exchange_block_kernel,
                         cudaFuncAttributeMaxDynamicSharedMemorySize, SMEM_BYTES);

    int dev = 0;
    cudaGetDevice(&dev);
    int sms = 148;
    cudaDeviceGetAttribute(&sms, cudaDevAttrMultiProcessorCount, dev);
    int grid = numTiles < sms ? numTiles : sms;

    exchange_block_kernel<<<grid, NTHREADS, SMEM_BYTES>>>(x, ev, W, b, out, n, numTiles);
}

// round 9
// speedup vs baseline: 2.6809x; 2.6809x over previous
#include <cuda_runtime.h>
#include <cuda_bf16.h>
#include <cstdint>

#define F_DIM   132
#define M_TOTAL 24
#define D_IN    136
#define BM      128
#define KS      152                 // bf16 per row (136 data + pad)
#define KSB     304                 // row stride bytes
#define NROWS_B 144
#define NT      256

#define B_BYTES (NROWS_B * KSB)     // 43776
#define A_BYTES (BM * KSB)          // 38912
#define SM_BIAS 0                   // 136 floats
#define SM_BH   1024
#define SM_BL   (SM_BH + B_BYTES)   // 44800
#define SM_AH   (SM_BL + B_BYTES)   // 88576
#define SM_AL   (SM_AH + A_BYTES)   // 127488
#define SM_TOTAL (SM_AL + A_BYTES)  // 166400

typedef unsigned int u32;

__device__ __forceinline__ u32 smem_u32(const void* p) {
    u32 a;
    asm("{ .reg .u64 t; cvta.to.shared.u64 t, %1; cvt.u32.u64 %0, t; }"
        : "=r"(a) : "l"(p));
    return a;
}

__device__ __forceinline__ void ldmat4(u32* r, u32 addr) {
    asm volatile("ldmatrix.sync.aligned.m8n8.x4.shared.b16 {%0,%1,%2,%3}, [%4];"
        : "=r"(r[0]), "=r"(r[1]), "=r"(r[2]), "=r"(r[3]) : "r"(addr));
}
__device__ __forceinline__ void ldmat2(u32* r, u32 addr) {
    asm volatile("ldmatrix.sync.aligned.m8n8.x2.shared.b16 {%0,%1}, [%2];"
        : "=r"(r[0]), "=r"(r[1]) : "r"(addr));
}
__device__ __forceinline__ void mma_bf16(float* c, const u32* a, const u32* b) {
    asm volatile("mma.sync.aligned.m16n8k16.row.col.f32.bf16.bf16.f32 "
        "{%0,%1,%2,%3}, {%4,%5,%6,%7}, {%8,%9}, {%0,%1,%2,%3};"
        : "+f"(c[0]), "+f"(c[1]), "+f"(c[2]), "+f"(c[3])
        : "r"(a[0]), "r"(a[1]), "r"(a[2]), "r"(a[3]), "r"(b[0]), "r"(b[1]));
}

// bf16 hi/lo split of two fp32 values; hi/lo packed bf16x2 (first value -> low half)
__device__ __forceinline__ void split2(float a, float b, u32& hi, u32& lo) {
    __nv_bfloat16 ha = __float2bfloat16(a);
    __nv_bfloat16 hb = __float2bfloat16(b);
    __nv_bfloat16 la = __float2bfloat16(a - __bfloat162float(ha));
    __nv_bfloat16 lb = __float2bfloat16(b - __bfloat162float(hb));
    hi = ((u32)__bfloat16_as_ushort(hb) << 16) | (u32)__bfloat16_as_ushort(ha);
    lo = ((u32)__bfloat16_as_ushort(lb) << 16) | (u32)__bfloat16_as_ushort(la);
}

__global__ __launch_bounds__(NT, 1)
void exchange_mma_kernel(const float* __restrict__ x,
                         const float* __restrict__ ev,
                         const float* __restrict__ W,
                         const float* __restrict__ b,
                         float* __restrict__ out,
                         int n, int numTiles)
{
    extern __shared__ char smem[];
    const u32 sb = smem_u32(smem);
    const int tid  = threadIdx.x;
    const int lane = tid & 31;
    const int w    = tid >> 5;
    float* bs = (float*)(smem + SM_BIAS);
    float* out2base = out + (size_t)n * F_DIM;

    // ---- one-time: zero B, load bias ----
    for (int i = tid; i < (2 * B_BYTES) / 16; i += NT)
        ((uint4*)(smem + SM_BH))[i] = make_uint4(0u, 0u, 0u, 0u);
    for (int i = tid; i < D_IN; i += NT)
        bs[i] = b[i];
    __syncthreads();

    // ---- build Bh/Bl = bf16 hi/lo of W^T: Bs[n][k] = W[k][n] ----
    for (int idx = tid; idx < D_IN * D_IN; idx += NT) {
        int kk = idx / D_IN;
        int nn = idx % D_IN;
        float wv = W[idx];
        __nv_bfloat16 h = __float2bfloat16(wv);
        __nv_bfloat16 l = __float2bfloat16(wv - __bfloat162float(h));
        *(__nv_bfloat16*)(smem + SM_BH + nn * KSB + kk * 2) = h;
        *(__nv_bfloat16*)(smem + SM_BL + nn * KSB + kk * 2) = l;
    }

    // ---- per-lane fragment addresses ----
    const u32 aRow = (u32)((lane & 7) + ((lane >> 3) & 1) * 8);
    const u32 aK   = (u32)(((lane >> 4) & 1) * 16);
    const u32 aAddr = sb + SM_AH + (w * 16 + aRow) * KSB + aK;
    const u32 bRow = (u32)((lane & 7) + ((lane >> 4) & 1) * 8);
    const u32 bK   = (u32)(((lane >> 3) & 1) * 16);
    const u32 bAddr = sb + SM_BH + bRow * KSB + bK;

    const int r = tid >> 1;     // staging row within tile
    const int h = tid & 1;      // staging half

    for (int tile = blockIdx.x; tile < numTiles; tile += gridDim.x) {
        const int rowBase = tile * BM;
        __syncthreads();   // previous tile's compute done before restaging A

        // ================= stage A tile (2 threads per row) =================
        {
            const int row = rowBase + r;
            const bool valid = row < n;
            const float4* xrow = (const float4*)(x + (size_t)row * F_DIM);
            const float4 zf4 = make_float4(0.f, 0.f, 0.f, 0.f);
            float4 xr[17];
            float c0 = 0.f, c1 = 0.f, c2 = 0.f, c3 = 0.f;

            if (h == 0) {
                #pragma unroll
                for (int i = 0; i < 8; i++) {
                    xr[2 * i]     = valid ? xrow[4 * i]     : zf4;
                    xr[2 * i + 1] = valid ? xrow[4 * i + 1] : zf4;
                }
                xr[16] = valid ? xrow[32] : zf4;
                if (valid) {
                    const float4* er = (const float4*)(ev + (size_t)row * M_TOTAL);
                    float e[24];
                    #pragma unroll
                    for (int i = 0; i < 6; i++) {
                        float4 v = er[i];
                        e[4 * i] = v.x; e[4 * i + 1] = v.y;
                        e[4 * i + 2] = v.z; e[4 * i + 3] = v.w;
                    }
                    #pragma unroll
                    for (int m = 0;  m < 3;  m++) c0 += e[m] * e[m];
                    #pragma unroll
                    for (int m = 3;  m < 8;  m++) c1 += e[m] * e[m];
                    #pragma unroll
                    for (int m = 8;  m < 15; m++) c2 += e[m] * e[m];
                    #pragma unroll
                    for (int m = 15; m < 24; m++) c3 += e[m] * e[m];
                }
            } else {
                #pragma unroll
                for (int i = 0; i < 8; i++) {
                    xr[2 * i]     = valid ? xrow[4 * i + 2] : zf4;
                    xr[2 * i + 1] = valid ? xrow[4 * i + 3] : zf4;
                }
            }

            char* Ah = smem + SM_AH + r * KSB;
            char* Al = smem + SM_AL + r * KSB;
            #pragma unroll
            for (int i = 0; i < 8; i++) {
                int c = 2 * i + h;
                uint4 hi, lo;
                split2(xr[2 * i].x,     xr[2 * i].y,     hi.x, lo.x);
                split2(xr[2 * i].z,     xr[2 * i].w,     hi.y, lo.y);
                split2(xr[2 * i + 1].x, xr[2 * i + 1].y, hi.z, lo.z);
                split2(xr[2 * i + 1].z, xr[2 * i + 1].w, hi.w, lo.w);
                *(uint4*)(Ah + c * 16) = hi;
                *(uint4*)(Al + c * 16) = lo;
            }
            if (h == 0) {      // chunk 16: x[128..131] + contr[132..135]
                uint4 hi, lo;
                split2(xr[16].x, xr[16].y, hi.x, lo.x);
                split2(xr[16].z, xr[16].w, hi.y, lo.y);
                split2(c0, c1, hi.z, lo.z);
                split2(c2, c3, hi.w, lo.w);
                *(uint4*)(Ah + 256) = hi;
                *(uint4*)(Al + 256) = lo;
            } else {           // chunk 17: k 136..143 zero pad
                uint4 z = make_uint4(0u, 0u, 0u, 0u);
                *(uint4*)(Ah + 272) = z;
                *(uint4*)(Al + 272) = z;
            }
        }
        __syncthreads();

        // ================= compute: 459 HMMA per warp =================
        float acc[17][4];
        #pragma unroll
        for (int nc = 0; nc < 17; nc++)
            #pragma unroll
            for (int q = 0; q < 4; q++)
                acc[nc][q] = 0.f;

        #pragma unroll 1
        for (int s = 0; s < 9; s++) {
            u32 ah[4], al[4];
            ldmat4(ah, aAddr + s * 32);
            ldmat4(al, aAddr + s * 32 + A_BYTES);
            #pragma unroll
            for (int p = 0; p < 8; p++) {
                u32 bh[4], bl[4];
                u32 ba = bAddr + (u32)(p * 16 * KSB) + (u32)(s * 32);
                ldmat4(bh, ba);
                ldmat4(bl, ba + B_BYTES);
                mma_bf16(acc[2 * p],     ah, bh);
                mma_bf16(acc[2 * p + 1], ah, bh + 2);
                mma_bf16(acc[2 * p],     ah, bl);
                mma_bf16(acc[2 * p + 1], ah, bl + 2);
                mma_bf16(acc[2 * p],     al, bh);
                mma_bf16(acc[2 * p + 1], al, bh + 2);
            }
            {   // n-chunk 16 (cols 128..135)
                u32 bh2[2], bl2[2];
                u32 ba = bAddr + (u32)(8 * 16 * KSB) + (u32)(s * 32);
                ldmat2(bh2, ba);
                ldmat2(bl2, ba + B_BYTES);
                mma_bf16(acc[16], ah, bh2);
                mma_bf16(acc[16], ah, bl2);
                mma_bf16(acc[16], al, bh2);
            }
        }

        // ================= epilogue: direct fragment stores =================
        const int r0 = rowBase + w * 16 + (lane >> 2);
        const int r1 = r0 + 8;
        const int cp = lane & 3;

        #pragma unroll
        for (int nc = 0; nc < 17; nc++) {
            int col = nc * 8 + cp * 2;
            if (col < F_DIM) {
                float b0 = bs[col], b1 = bs[col + 1];
                if (r0 < n)
                    *(float2*)(out + (size_t)r0 * F_DIM + col) =
                        make_float2(acc[nc][0] + b0, acc[nc][1] + b1);
                if (r1 < n)
                    *(float2*)(out + (size_t)r1 * F_DIM + col) =
                        make_float2(acc[nc][2] + b0, acc[nc][3] + b1);
            }
        }

        // cols 132..135 gate ev -> out2 (fragment nc=16, cp in {2,3})
        {
            int col = 128 + cp * 2;
            float b0 = (cp >= 2) ? bs[col]     : 0.f;
            float b1 = (cp >= 2) ? bs[col + 1] : 0.f;
            float o0 = acc[16][0] + b0, o1 = acc[16][1] + b1;
            float o2 = acc[16][2] + b0, o3 = acc[16][3] + b1;
            float p0 = __shfl_xor_sync(0xffffffffu, o0, 1);
            float p1 = __shfl_xor_sync(0xffffffffu, o1, 1);
            float p2 = __shfl_xor_sync(0xffffffffu, o2, 1);
            float p3 = __shfl_xor_sync(0xffffffffu, o3, 1);
            if (cp == 2) {
                #pragma unroll
                for (int half = 0; half < 2; half++) {
                    int rr = half ? r1 : r0;
                    float g0 = half ? o2 : o0;
                    float g1 = half ? o3 : o1;
                    float g2 = half ? p2 : p0;
                    float g3 = half ? p3 : p1;
                    if (rr < n) {
                        const float4* er = (const float4*)(ev + (size_t)rr * M_TOTAL);
                        float e[24];
                        #pragma unroll
                        for (int i = 0; i < 6; i++) {
                            float4 v = er[i];
                            e[4 * i] = v.x; e[4 * i + 1] = v.y;
                            e[4 * i + 2] = v.z; e[4 * i + 3] = v.w;
                        }
                        float o[24];
                        #pragma unroll
                        for (int m = 0;  m < 3;  m++) o[m] = g0 * e[m];
                        #pragma unroll
                        for (int m = 3;  m < 8;  m++) o[m] = g1 * e[m];
                        #pragma unroll
                        for (int m = 8;  m < 15; m++) o[m] = g2 * e[m];
                        #pragma unroll
                        for (int m = 15; m < 24; m++) o[m] = g3 * e[m];
                        float* od = out2base + (size_t)rr * M_TOTAL;
                        #pragma unroll
                        for (int q = 0; q < 6; q++)
                            *(float4*)(od + q * 4) = make_float4(
                                o[q * 4], o[q * 4 + 1], o[q * 4 + 2], o[q * 4 + 3]);
                    }
                }
            }
        }
    }
}

extern "C" void kernel_launch(void* const* d_in, const int* in_sizes, int n_in,
                              void* d_out, int out_size)
{
    const float* x  = (const float*)d_in[0];
    const float* ev = (const float*)d_in[1];
    const float* W  = (const float*)d_in[2];
    const float* b  = (const float*)d_in[3];
    float* out = (float*)d_out;

    const int n = in_sizes[0] / F_DIM;
    const int numTiles = (n + BM - 1) / BM;

    cudaFuncSetAttribute(exchange_mma_kernel,
                         cudaFuncAttributeMaxDynamicSharedMemorySize, SM_TOTAL);

    int dev = 0;
    cudaGetDevice(&dev);
    int sms = 148;
    cudaDeviceGetAttribute(&sms, cudaDevAttrMultiProcessorCount, dev);
    int grid = numTiles < sms ? numTiles : sms;

    exchange_mma_kernel<<<grid, NT, SM_TOTAL>>>(x, ev, W, b, out, n, numTiles);
}